// round 2
// baseline (speedup 1.0000x reference)
#include <cuda_runtime.h>
#include <stdint.h>

// Problem constants
#define NB   32              // batch
#define NC   64              // channels
#define NW   32
#define NH   32
#define NN   1024            // NW*NH
#define NHEADS 4
#define ND   16              // head dim
#define NDA  32              // augmented dim (k~ = [k;q], q~ = [q;pos])

typedef unsigned long long ull;

// ---------------- scratch (device globals, no allocation) ----------------
__device__ float g_q[NB * NC * NN];      // [b][c][n], c = head*16+d
__device__ float g_k[NB * NC * NN];
__device__ float g_v[NB * NC * NN];
__device__ float g_att[NB * NC * NN];    // attention output (pre-LN)
__device__ float g_chatt[NB * NC];       // channel attention
__device__ float g_sp[NB * NN];          // spatial attention map
__device__ float g_stats[NB * 2];        // LN mu, rstd per batch

// ---------------- f32x2 helpers (FFMA2 path, sm_103a) ----------------
__device__ __forceinline__ ull fma2(ull a, ull b, ull c) {
    ull d;
    asm("fma.rn.f32x2 %0, %1, %2, %3;" : "=l"(d) : "l"(a), "l"(b), "l"(c));
    return d;
}
__device__ __forceinline__ ull pack2(float lo, float hi) {
    ull r;
    asm("mov.b64 %0, {%1, %2};" : "=l"(r) : "f"(lo), "f"(hi));
    return r;
}
__device__ __forceinline__ float2 unpack2(ull v) {
    float2 r;
    asm("mov.b64 {%0, %1}, %2;" : "=f"(r.x), "=f"(r.y) : "l"(v));
    return r;
}

// =====================================================================
// K1: QKV 1x1-conv projection.  For each b:  Q = Wq @ X_b  (+bias), etc.
// grid = NB*4 (256 spatial cols per block), 512 threads.
// smem: xs[64][256] + ws[3][64][66]  (weights stored [m][c][o], o contiguous,
// padded to 66 so transposed fill has only 2-way bank conflicts and o-pair
// ull loads stay 8B aligned).
// Each thread: 2 n-columns x 16 o (o-pair packed f32x2) x 3 matrices.
// =====================================================================
__global__ void __launch_bounds__(512, 1)
qkv_kernel(const float* __restrict__ x,
           const float* __restrict__ Wq, const float* __restrict__ bq,
           const float* __restrict__ Wk, const float* __restrict__ bk,
           const float* __restrict__ Wv, const float* __restrict__ bv)
{
    extern __shared__ float sm1[];
    float* xs = sm1;               // 64*256
    float* ws = sm1 + 64 * 256;    // 3*64*66

    const int b  = blockIdx.x >> 2;
    const int n0 = (blockIdx.x & 3) << 8;
    const int tid = threadIdx.x;

    const float* xb = x + b * (NC * NN);
    for (int idx = tid; idx < 64 * 256; idx += 512) {
        int c = idx >> 8, nl = idx & 255;
        xs[idx] = xb[c * NN + n0 + nl];
    }
    {
        const float* wsrc[3] = {Wq, Wk, Wv};
        for (int m = 0; m < 3; m++) {
            const float* w = wsrc[m];
            for (int idx = tid; idx < 4096; idx += 512) {
                int o = idx >> 6, c = idx & 63;
                ws[m * 4224 + c * 66 + o] = w[idx];   // w[o*64+c]
            }
        }
    }
    __syncthreads();

    const int nl = (tid & 127) << 1;      // 2 n per thread
    const int og = (tid >> 7) << 4;       // 16 o per thread

    ull acc[3][8][2];
    {
        const float* bias[3] = {bq, bk, bv};
#pragma unroll
        for (int m = 0; m < 3; m++)
#pragma unroll
            for (int p = 0; p < 8; p++) {
                float b0 = bias[m][og + 2 * p];
                float b1 = bias[m][og + 2 * p + 1];
                ull bb = pack2(b0, b1);
                acc[m][p][0] = bb;
                acc[m][p][1] = bb;
            }
    }

#pragma unroll 4
    for (int c = 0; c < 64; c++) {
        float xv0 = xs[c * 256 + nl];
        float xv1 = xs[c * 256 + nl + 1];
        ull x0 = pack2(xv0, xv0);
        ull x1 = pack2(xv1, xv1);
#pragma unroll
        for (int m = 0; m < 3; m++) {
            const ull* wrow = (const ull*)&ws[m * 4224 + c * 66 + og];
#pragma unroll
            for (int p = 0; p < 8; p++) {
                ull w2 = wrow[p];
                acc[m][p][0] = fma2(x0, w2, acc[m][p][0]);
                acc[m][p][1] = fma2(x1, w2, acc[m][p][1]);
            }
        }
    }

    {
        float* dsts[3] = {g_q, g_k, g_v};
#pragma unroll
        for (int m = 0; m < 3; m++) {
            float* dst = dsts[m] + b * (NC * NN);
#pragma unroll
            for (int p = 0; p < 8; p++) {
                float2 a0 = unpack2(acc[m][p][0]);   // (o, o+1) @ n0+nl
                float2 a1 = unpack2(acc[m][p][1]);   // (o, o+1) @ n0+nl+1
                int o = og + 2 * p;
                *(float2*)&dst[o * NN + n0 + nl]       = make_float2(a0.x, a1.x);
                *(float2*)&dst[(o + 1) * NN + n0 + nl] = make_float2(a0.y, a1.y);
            }
        }
    }
}

// =====================================================================
// K2: attention per (b, head).  grid = 128, 512 threads, ~208KB smem.
// k~[j][d]  (d=0..15 : K, 16..31 : Q)  row stride 34 (pad: 2-way conflicts,
// 8B alignment preserved).  v[j][d] stride 18.
// Each thread owns queries i = tid and tid+512.
// Scores: f32x2 packed over d-pairs; V accum: f32x2 packed over d-pairs.
// Softmax without running max (|s| <= ~14, exp cannot overflow fp32).
// =====================================================================
__global__ void __launch_bounds__(512, 1)
attn_kernel(const float* __restrict__ rel_h, const float* __restrict__ rel_w)
{
    extern __shared__ float sm2[];
    float* ksm = sm2;                 // [1024][34]
    float* vsm = sm2 + 1024 * 34;     // [1024][18]

    const int b  = blockIdx.x >> 2;
    const int hh = blockIdx.x & 3;
    const int tid = threadIdx.x;

    const float* qb = g_q + b * (NC * NN) + hh * (ND * NN);
    const float* kb = g_k + b * (NC * NN) + hh * (ND * NN);
    const float* vb = g_v + b * (NC * NN) + hh * (ND * NN);

    for (int j = tid; j < NN; j += 512) {
#pragma unroll
        for (int d = 0; d < ND; d++) {
            ksm[j * 34 + d]      = kb[d * NN + j];
            ksm[j * 34 + 16 + d] = qb[d * NN + j];
            vsm[j * 18 + d]      = vb[d * NN + j];
        }
    }

    // q~ for this thread's 2 queries, packed over d-pairs
    ull qa[2][16];
#pragma unroll
    for (int r = 0; r < 2; r++) {
        int i  = tid + r * 512;
        int iw = i >> 5, ih = i & 31;
#pragma unroll
        for (int dd = 0; dd < 16; dd++) {
            int d0 = 2 * dd, d1 = d0 + 1;
            float v0, v1;
            if (d0 < 16) {
                v0 = qb[d0 * NN + i];
                v1 = qb[d1 * NN + i];
            } else {
                int e0 = d0 - 16, e1 = d1 - 16;
                v0 = rel_h[(hh * ND + e0) * 32 + ih] + rel_w[(hh * ND + e0) * 32 + iw];
                v1 = rel_h[(hh * ND + e1) * 32 + ih] + rel_w[(hh * ND + e1) * 32 + iw];
            }
            qa[r][dd] = pack2(v0, v1);
        }
    }
    __syncthreads();

    ull acc[2][8];
#pragma unroll
    for (int r = 0; r < 2; r++)
#pragma unroll
        for (int dd = 0; dd < 8; dd++) acc[r][dd] = 0ULL;
    float l0 = 0.f, l1 = 0.f;

    for (int j = 0; j < NN; j++) {
        const ull* kj = (const ull*)&ksm[j * 34];
        ull sA = 0ULL, sB = 0ULL;
#pragma unroll
        for (int dd = 0; dd < 16; dd++) {
            ull kk = kj[dd];
            sA = fma2(qa[0][dd], kk, sA);
            sB = fma2(qa[1][dd], kk, sB);
        }
        float2 a  = unpack2(sA);
        float2 bb = unpack2(sB);
        float p0 = __expf(a.x + a.y);
        float p1 = __expf(bb.x + bb.y);
        l0 += p0;
        l1 += p1;
        const ull* vj = (const ull*)&vsm[j * 18];
        ull pp0 = pack2(p0, p0);
        ull pp1 = pack2(p1, p1);
#pragma unroll
        for (int dd = 0; dd < 8; dd++) {
            ull vv = vj[dd];
            acc[0][dd] = fma2(pp0, vv, acc[0][dd]);
            acc[1][dd] = fma2(pp1, vv, acc[1][dd]);
        }
    }

    float* ob = g_att + b * (NC * NN) + hh * (ND * NN);
    float inv0 = 1.f / l0, inv1 = 1.f / l1;
#pragma unroll
    for (int dd = 0; dd < 8; dd++) {
        float2 o0 = unpack2(acc[0][dd]);
        float2 o1 = unpack2(acc[1][dd]);
        ob[(2 * dd) * NN + tid]           = o0.x * inv0;
        ob[(2 * dd + 1) * NN + tid]       = o0.y * inv0;
        ob[(2 * dd) * NN + tid + 512]     = o1.x * inv1;
        ob[(2 * dd + 1) * NN + tid + 512] = o1.y * inv1;
    }
}

// =====================================================================
// K3: per-batch reductions: LN mean/var over att output; x avg/max per
// channel; CBAM channel MLP -> sigmoid.  grid = NB, 256 threads.
// =====================================================================
__global__ void __launch_bounds__(256)
stats_kernel(const float* __restrict__ x,
             const float* __restrict__ ca_w1, const float* __restrict__ ca_b1,
             const float* __restrict__ ca_w2, const float* __restrict__ ca_b2)
{
    const int b = blockIdx.x, tid = threadIdx.x;
    __shared__ float r1[256], r2[256];
    __shared__ float savg[64], smx2[64], hid[8];

    // LayerNorm stats over g_att[b] (65536 elems)
    const float* ab = g_att + b * (NC * NN);
    float s = 0.f, ss = 0.f;
    for (int idx = tid; idx < NC * NN; idx += 256) {
        float v = ab[idx];
        s += v;
        ss += v * v;
    }
    r1[tid] = s; r2[tid] = ss;
    __syncthreads();
    for (int off = 128; off > 0; off >>= 1) {
        if (tid < off) { r1[tid] += r1[tid + off]; r2[tid] += r2[tid + off]; }
        __syncthreads();
    }
    if (tid == 0) {
        float mu  = r1[0] * (1.f / 65536.f);
        float var = r2[0] * (1.f / 65536.f) - mu * mu;
        g_stats[2 * b]     = mu;
        g_stats[2 * b + 1] = rsqrtf(var + 1e-5f);
    }
    __syncthreads();

    // per-channel avg / max of x
    {
        int c = tid >> 2, qq = tid & 3;
        const float* xc = x + b * (NC * NN) + c * NN + qq * 256;
        float sa = 0.f, mx = -3.4e38f;
        for (int t = 0; t < 256; t++) {
            float v = xc[t];
            sa += v;
            mx = fmaxf(mx, v);
        }
        r1[tid] = sa; r2[tid] = mx;
    }
    __syncthreads();
    if (tid < 64) {
        float av = 0.f, m = -3.4e38f;
        for (int q2 = 0; q2 < 4; q2++) {
            av += r1[tid * 4 + q2];
            m = fmaxf(m, r2[tid * 4 + q2]);
        }
        savg[tid] = av * (1.f / 1024.f);
        smx2[tid] = m;
    }
    __syncthreads();
    if (tid < 8) {
        int r = tid & 3;
        const float* src = (tid < 4) ? savg : smx2;
        float h = ca_b1[r];
        for (int c2 = 0; c2 < 64; c2++) h += ca_w1[r * 64 + c2] * src[c2];
        hid[tid] = fmaxf(h, 0.f);
    }
    __syncthreads();
    if (tid < 64) {
        float o = 2.f * ca_b2[tid];            // b2 appears in both MLP calls
        for (int r = 0; r < 4; r++) o += ca_w2[tid * 4 + r] * (hid[r] + hid[4 + r]);
        g_chatt[b * NC + tid] = 1.f / (1.f + __expf(-o));
    }
}

// =====================================================================
// K4a: CBAM spatial map.  grid = NB, 1024 threads (one per spatial pos).
// feat = [mean_c(ch*x), max_c(ch*x)] ; 7x7 SAME conv ; sigmoid.
// =====================================================================
__global__ void __launch_bounds__(1024)
spatial_kernel(const float* __restrict__ x,
               const float* __restrict__ sa_w, const float* __restrict__ sa_b)
{
    const int b = blockIdx.x, tid = threadIdx.x;
    __shared__ float fm[NN], fx[NN], chs[64], wsh[98];
    if (tid < 64) chs[tid] = g_chatt[b * NC + tid];
    if (tid < 98) wsh[tid] = sa_w[tid];
    __syncthreads();

    {
        const float* xb = x + b * (NC * NN) + tid;
        float s = 0.f, m = -3.4e38f;
#pragma unroll
        for (int c = 0; c < 64; c++) {
            float v = chs[c] * xb[c * NN];
            s += v;
            m = fmaxf(m, v);
        }
        fm[tid] = s * (1.f / 64.f);
        fx[tid] = m;
    }
    __syncthreads();

    const int iw = tid >> 5, ih = tid & 31;
    float o = sa_b[0];
#pragma unroll
    for (int ky = 0; ky < 7; ky++) {
        int y = iw + ky - 3;
        if ((unsigned)y < 32u) {
#pragma unroll
            for (int kx = 0; kx < 7; kx++) {
                int xx2 = ih + kx - 3;
                if ((unsigned)xx2 < 32u) {
                    int fi = y * 32 + xx2;
                    o += wsh[ky * 7 + kx] * fm[fi] + wsh[49 + ky * 7 + kx] * fx[fi];
                }
            }
        }
    }
    g_sp[b * NN + tid] = 1.f / (1.f + __expf(-o));
}

// =====================================================================
// K4b: final fuse:  out = LN(att)*g+b + 2x + sp*ch*x
//      (mhsa + cbam + x = (ln + x) + sp*ch*x + x)
// grid = 8192 x 256 (one thread per element).
// =====================================================================
__global__ void __launch_bounds__(256)
final_kernel(const float* __restrict__ x,
             const float* __restrict__ ln_g, const float* __restrict__ ln_b,
             float* __restrict__ out)
{
    int idx = blockIdx.x * 256 + threadIdx.x;       // 0 .. 2097151
    int b  = idx >> 16;
    int cn = idx & 65535;
    int c  = cn >> 10;
    int n  = cn & 1023;

    float mu   = g_stats[2 * b];
    float rstd = g_stats[2 * b + 1];
    float xv = x[idx];
    float av = g_att[idx];
    float ln = (av - mu) * rstd * ln_g[cn] + ln_b[cn];
    out[idx] = ln + 2.f * xv + g_sp[b * NN + n] * g_chatt[b * NC + c] * xv;
}

// =====================================================================
extern "C" void kernel_launch(void* const* d_in, const int* in_sizes, int n_in,
                              void* d_out, int out_size)
{
    const float* x     = (const float*)d_in[0];
    const float* Wq    = (const float*)d_in[1];
    const float* bq    = (const float*)d_in[2];
    const float* Wk    = (const float*)d_in[3];
    const float* bk    = (const float*)d_in[4];
    const float* Wv    = (const float*)d_in[5];
    const float* bv    = (const float*)d_in[6];
    const float* rel_h = (const float*)d_in[7];
    const float* rel_w = (const float*)d_in[8];
    const float* ln_g  = (const float*)d_in[9];
    const float* ln_b  = (const float*)d_in[10];
    const float* ca_w1 = (const float*)d_in[11];
    const float* ca_b1 = (const float*)d_in[12];
    const float* ca_w2 = (const float*)d_in[13];
    const float* ca_b2 = (const float*)d_in[14];
    const float* sa_w  = (const float*)d_in[15];
    const float* sa_b  = (const float*)d_in[16];
    float* out = (float*)d_out;

    const int smem1 = (64 * 256 + 3 * 64 * 66) * (int)sizeof(float);   // ~116 KB
    const int smem2 = (1024 * 34 + 1024 * 18) * (int)sizeof(float);    // ~208 KB
    cudaFuncSetAttribute(qkv_kernel,  cudaFuncAttributeMaxDynamicSharedMemorySize, smem1);
    cudaFuncSetAttribute(attn_kernel, cudaFuncAttributeMaxDynamicSharedMemorySize, smem2);

    qkv_kernel<<<NB * 4, 512, smem1>>>(x, Wq, bq, Wk, bk, Wv, bv);
    attn_kernel<<<NB * NHEADS, 512, smem2>>>(rel_h, rel_w);
    stats_kernel<<<NB, 256>>>(x, ca_w1, ca_b1, ca_w2, ca_b2);
    spatial_kernel<<<NB, 1024>>>(x, sa_w, sa_b);
    final_kernel<<<(NB * NC * NN) / 256, 256>>>(x, ln_g, ln_b, out);
}

// round 8
// speedup vs baseline: 1.9495x; 1.9495x over previous
#include <cuda_runtime.h>
#include <cuda_bf16.h>
#include <stdint.h>

// Problem constants
#define NB   32
#define NC   64
#define NN   1024
#define NHEADS 4
#define ND   16

typedef unsigned long long ull;

// ---------------- scratch (device globals) ----------------
__device__ float g_q[NB * NC * NN];
__device__ float g_k[NB * NC * NN];
__device__ float g_v[NB * NC * NN];
__device__ float g_att[NB * NC * NN];
__device__ float g_chatt[NB * NC];
__device__ float g_sp[NB * NN];
__device__ float g_stats[NB * 2];

// ---------------- f32x2 helpers (qkv kernel) ----------------
__device__ __forceinline__ ull fma2(ull a, ull b, ull c) {
    ull d;
    asm("fma.rn.f32x2 %0, %1, %2, %3;" : "=l"(d) : "l"(a), "l"(b), "l"(c));
    return d;
}
__device__ __forceinline__ ull pack2(float lo, float hi) {
    ull r;
    asm("mov.b64 %0, {%1, %2};" : "=l"(r) : "f"(lo), "f"(hi));
    return r;
}
__device__ __forceinline__ float2 unpack2(ull v) {
    float2 r;
    asm("mov.b64 {%0, %1}, %2;" : "=f"(r.x), "=f"(r.y) : "l"(v));
    return r;
}
// MUFU exp2 (device-safe, guaranteed EX2)
__device__ __forceinline__ float ex2(float x) {
    float r;
    asm("ex2.approx.ftz.f32 %0, %1;" : "=f"(r) : "f"(x));
    return r;
}

// =====================================================================
// K1: QKV projection (validated in R2)
// =====================================================================
__global__ void __launch_bounds__(512, 1)
qkv_kernel(const float* __restrict__ x,
           const float* __restrict__ Wq, const float* __restrict__ bq,
           const float* __restrict__ Wk, const float* __restrict__ bk,
           const float* __restrict__ Wv, const float* __restrict__ bv)
{
    extern __shared__ float sm1[];
    float* xs = sm1;
    float* ws = sm1 + 64 * 256;

    const int b  = blockIdx.x >> 2;
    const int n0 = (blockIdx.x & 3) << 8;
    const int tid = threadIdx.x;

    const float* xb = x + b * (NC * NN);
    for (int idx = tid; idx < 64 * 256; idx += 512) {
        int c = idx >> 8, nl = idx & 255;
        xs[idx] = xb[c * NN + n0 + nl];
    }
    {
        const float* wsrc[3] = {Wq, Wk, Wv};
        for (int m = 0; m < 3; m++) {
            const float* w = wsrc[m];
            for (int idx = tid; idx < 4096; idx += 512) {
                int o = idx >> 6, c = idx & 63;
                ws[m * 4224 + c * 66 + o] = w[idx];
            }
        }
    }
    __syncthreads();

    const int nl = (tid & 127) << 1;
    const int og = (tid >> 7) << 4;

    ull acc[3][8][2];
    {
        const float* bias[3] = {bq, bk, bv};
#pragma unroll
        for (int m = 0; m < 3; m++)
#pragma unroll
            for (int p = 0; p < 8; p++) {
                ull bb = pack2(bias[m][og + 2 * p], bias[m][og + 2 * p + 1]);
                acc[m][p][0] = bb;
                acc[m][p][1] = bb;
            }
    }

#pragma unroll 4
    for (int c = 0; c < 64; c++) {
        float xv0 = xs[c * 256 + nl];
        float xv1 = xs[c * 256 + nl + 1];
        ull x0 = pack2(xv0, xv0);
        ull x1 = pack2(xv1, xv1);
#pragma unroll
        for (int m = 0; m < 3; m++) {
            const ull* wrow = (const ull*)&ws[m * 4224 + c * 66 + og];
#pragma unroll
            for (int p = 0; p < 8; p++) {
                ull w2 = wrow[p];
                acc[m][p][0] = fma2(x0, w2, acc[m][p][0]);
                acc[m][p][1] = fma2(x1, w2, acc[m][p][1]);
            }
        }
    }

    {
        float* dsts[3] = {g_q, g_k, g_v};
#pragma unroll
        for (int m = 0; m < 3; m++) {
            float* dst = dsts[m] + b * (NC * NN);
#pragma unroll
            for (int p = 0; p < 8; p++) {
                float2 a0 = unpack2(acc[m][p][0]);
                float2 a1 = unpack2(acc[m][p][1]);
                int o = og + 2 * p;
                *(float2*)&dst[o * NN + n0 + nl]       = make_float2(a0.x, a1.x);
                *(float2*)&dst[(o + 1) * NN + n0 + nl] = make_float2(a0.y, a1.y);
            }
        }
    }
}

// =====================================================================
// mma.sync helpers (plain-target bf16 HMMA)
// =====================================================================
__device__ __forceinline__ void mma16816(float& d0, float& d1, float& d2, float& d3,
    uint32_t a0, uint32_t a1, uint32_t a2, uint32_t a3,
    uint32_t b0, uint32_t b1,
    float c0, float c1, float c2, float c3)
{
    asm("mma.sync.aligned.m16n8k16.row.col.f32.bf16.bf16.f32 "
        "{%0,%1,%2,%3}, {%4,%5,%6,%7}, {%8,%9}, {%10,%11,%12,%13};"
        : "=f"(d0), "=f"(d1), "=f"(d2), "=f"(d3)
        : "r"(a0), "r"(a1), "r"(a2), "r"(a3), "r"(b0), "r"(b1),
          "f"(c0), "f"(c1), "f"(c2), "f"(c3));
}
__device__ __forceinline__ void mma1688(float& d0, float& d1, float& d2, float& d3,
    uint32_t a0, uint32_t a1, uint32_t b0,
    float c0, float c1, float c2, float c3)
{
    asm("mma.sync.aligned.m16n8k8.row.col.f32.bf16.bf16.f32 "
        "{%0,%1,%2,%3}, {%4,%5}, {%6}, {%7,%8,%9,%10};"
        : "=f"(d0), "=f"(d1), "=f"(d2), "=f"(d3)
        : "r"(a0), "r"(a1), "r"(b0),
          "f"(c0), "f"(c1), "f"(c2), "f"(c3));
}
// pack two f32 into bf16x2 (v1 -> high, v0 -> low) and produce hi/lo split pair
__device__ __forceinline__ uint32_t bpack(float v1, float v0) {
    uint32_t r;
    asm("cvt.rn.bf16x2.f32 %0, %1, %2;" : "=r"(r) : "f"(v1), "f"(v0));
    return r;
}
__device__ __forceinline__ void bsplit2(float v1, float v0, uint32_t& hi, uint32_t& lo) {
    uint32_t h = bpack(v1, v0);
    float h0 = __uint_as_float(h << 16);
    float h1 = __uint_as_float(h & 0xffff0000u);
    lo = bpack(v1 - h1, v0 - h0);
    hi = h;
}

// smem layout (bytes)
#define SM_KH   0              // K~ hi: [1024 rows][64B] XOR-swizzled
#define SM_KL   65536          // K~ lo
#define SM_VH   131072         // V hi: [16 rows][2064B]  (padded stride)
#define SM_VL   164096         // V lo
#define SM_TOT2 197120
#define VSTRIDE 2064

// =====================================================================
// K2: flash attention via mma.sync, 1 CTA per (b,head), 512 threads.
// S split terms: HH(k0), HH(k1), HL(k0), HL(k1), LH(k1 = pos_lo x q_hi).
// PV terms: P_hi x {V_hi, V_lo}, P_lo x V_hi.
// =====================================================================
__global__ void __launch_bounds__(512, 1)
attn_mma_kernel(const float* __restrict__ rel_h, const float* __restrict__ rel_w)
{
    extern __shared__ char sm[];
    const int tid  = threadIdx.x;
    const int warp = tid >> 5;
    const int lane = tid & 31;
    const int g = lane >> 2;      // group (row within tile)
    const int t = lane & 3;
    const int b  = blockIdx.x >> 2;
    const int hh = blockIdx.x & 3;

    const float* qb = g_q + b * (NC * NN) + hh * (ND * NN);
    const float* kb = g_k + b * (NC * NN) + hh * (ND * NN);
    const float* vb = g_v + b * (NC * NN) + hh * (ND * NN);

    // ---------------- fill K~ hi/lo ----------------
#pragma unroll
    for (int rep = 0; rep < 2; rep++) {
        const int j = tid + (rep << 9);
        const uint32_t base = (uint32_t)j << 6;
        const uint32_t xo = (uint32_t)((j & 7) << 3);
#pragma unroll
        for (int d = 0; d < 16; d += 2) {
            uint32_t hi, lo;
            bsplit2(kb[(d + 1) * NN + j], kb[d * NN + j], hi, lo);
            uint32_t off = base + ((uint32_t)(2 * d) ^ xo);
            *(uint32_t*)(sm + SM_KH + off) = hi;
            *(uint32_t*)(sm + SM_KL + off) = lo;
            bsplit2(qb[(d + 1) * NN + j], qb[d * NN + j], hi, lo);
            off = base + ((uint32_t)(32 + 2 * d) ^ xo);
            *(uint32_t*)(sm + SM_KH + off) = hi;
            *(uint32_t*)(sm + SM_KL + off) = lo;
        }
    }
    // ---------------- fill V hi/lo:  [d][j] rows, stride 2064B ----------------
    {
        const int j2 = tid << 1;
#pragma unroll
        for (int d = 0; d < 16; d++) {
            uint32_t hi, lo;
            bsplit2(vb[d * NN + j2 + 1], vb[d * NN + j2], hi, lo);
            *(uint32_t*)(sm + SM_VH + d * VSTRIDE + (tid << 2)) = hi;
            *(uint32_t*)(sm + SM_VL + d * VSTRIDE + (tid << 2)) = lo;
        }
    }

    // ---------------- build A (q~ * log2e) fragments ----------------
    const float L2E = 1.4426950408889634f;
    const int i0 = warp << 6;             // 64 rows per warp
    uint32_t qh[4][2][4];                 // [mtile][kchunk][a0..a3] hi
    uint32_t qlp[4][4];                   // [mtile][a0..a3] pos lo (chunk1)
#pragma unroll
    for (int mt = 0; mt < 4; mt++) {
        const int r0 = i0 + (mt << 4) + g;
        const int r1 = r0 + 8;
#pragma unroll
        for (int half = 0; half < 2; half++) {
            const int dA = 2 * t + half * 8;
            // chunk0: q * L2E, hi only (LH_k0 term dropped: sigma ~7e-4)
            qh[mt][0][half * 2 + 0] = bpack(qb[(dA + 1) * NN + r0] * L2E,
                                            qb[dA * NN + r0] * L2E);
            qh[mt][0][half * 2 + 1] = bpack(qb[(dA + 1) * NN + r1] * L2E,
                                            qb[dA * NN + r1] * L2E);
            // chunk1: pos * L2E, hi + lo (pos_lo x q_hi is the 0.0026 term)
            float p00 = (rel_h[(hh * ND + dA) * 32 + (r0 & 31)] +
                         rel_w[(hh * ND + dA) * 32 + (r0 >> 5)]) * L2E;
            float p01 = (rel_h[(hh * ND + dA + 1) * 32 + (r0 & 31)] +
                         rel_w[(hh * ND + dA + 1) * 32 + (r0 >> 5)]) * L2E;
            float p10 = (rel_h[(hh * ND + dA) * 32 + (r1 & 31)] +
                         rel_w[(hh * ND + dA) * 32 + (r1 >> 5)]) * L2E;
            float p11 = (rel_h[(hh * ND + dA + 1) * 32 + (r1 & 31)] +
                         rel_w[(hh * ND + dA + 1) * 32 + (r1 >> 5)]) * L2E;
            uint32_t hi, lo;
            bsplit2(p01, p00, hi, lo);
            qh[mt][1][half * 2 + 0] = hi;  qlp[mt][half * 2 + 0] = lo;
            bsplit2(p11, p10, hi, lo);
            qh[mt][1][half * 2 + 1] = hi;  qlp[mt][half * 2 + 1] = lo;
        }
    }
    __syncthreads();

    // ---------------- mainloop over 128 j-chunks of 8 ----------------
    float O[4][2][4];
    float l[4][2];
#pragma unroll
    for (int mt = 0; mt < 4; mt++) {
#pragma unroll
        for (int dn = 0; dn < 2; dn++)
#pragma unroll
            for (int r = 0; r < 4; r++) O[mt][dn][r] = 0.f;
        l[mt][0] = 0.f; l[mt][1] = 0.f;
    }

    const uint32_t xg = (uint32_t)(g << 3);
    const uint32_t o00 = ((uint32_t)(4 * t))      ^ xg;
    const uint32_t o01 = ((uint32_t)(16 + 4 * t)) ^ xg;
    const uint32_t o10 = ((uint32_t)(32 + 4 * t)) ^ xg;
    const uint32_t o11 = ((uint32_t)(48 + 4 * t)) ^ xg;
    const char* krowH = sm + SM_KH + (g << 6);
    const char* krowL = sm + SM_KL + (g << 6);
    const char* vrow0H = sm + SM_VH + g * VSTRIDE + (t << 2);
    const char* vrow1H = sm + SM_VH + (8 + g) * VSTRIDE + (t << 2);
    const char* vrow0L = sm + SM_VL + g * VSTRIDE + (t << 2);
    const char* vrow1L = sm + SM_VL + (8 + g) * VSTRIDE + (t << 2);

    for (int j8 = 0; j8 < 128; j8++) {
        const uint32_t jb = (uint32_t)j8 << 9;   // j0*64
        const uint32_t vjb = (uint32_t)j8 << 4;  // j0*2
        const uint32_t bh00 = *(const uint32_t*)(krowH + jb + o00);
        const uint32_t bh01 = *(const uint32_t*)(krowH + jb + o01);
        const uint32_t bh10 = *(const uint32_t*)(krowH + jb + o10);
        const uint32_t bh11 = *(const uint32_t*)(krowH + jb + o11);
        const uint32_t bl00 = *(const uint32_t*)(krowL + jb + o00);
        const uint32_t bl01 = *(const uint32_t*)(krowL + jb + o01);
        const uint32_t bl10 = *(const uint32_t*)(krowL + jb + o10);
        const uint32_t bl11 = *(const uint32_t*)(krowL + jb + o11);
        const uint32_t vh0 = *(const uint32_t*)(vrow0H + vjb);
        const uint32_t vh1 = *(const uint32_t*)(vrow1H + vjb);
        const uint32_t vl0 = *(const uint32_t*)(vrow0L + vjb);
        const uint32_t vl1 = *(const uint32_t*)(vrow1L + vjb);

#pragma unroll
        for (int mt = 0; mt < 4; mt++) {
            float d0, d1, d2, d3;
            mma16816(d0, d1, d2, d3, qh[mt][0][0], qh[mt][0][1], qh[mt][0][2], qh[mt][0][3],
                     bh00, bh01, 0.f, 0.f, 0.f, 0.f);                       // HH k0
            mma16816(d0, d1, d2, d3, qh[mt][1][0], qh[mt][1][1], qh[mt][1][2], qh[mt][1][3],
                     bh10, bh11, d0, d1, d2, d3);                           // HH k1
            mma16816(d0, d1, d2, d3, qh[mt][0][0], qh[mt][0][1], qh[mt][0][2], qh[mt][0][3],
                     bl00, bl01, d0, d1, d2, d3);                           // HL k0
            mma16816(d0, d1, d2, d3, qh[mt][1][0], qh[mt][1][1], qh[mt][1][2], qh[mt][1][3],
                     bl10, bl11, d0, d1, d2, d3);                           // HL k1
            mma16816(d0, d1, d2, d3, qlp[mt][0], qlp[mt][1], qlp[mt][2], qlp[mt][3],
                     bh10, bh11, d0, d1, d2, d3);                           // LH k1 (pos_lo)
            // softmax numerators via MUFU EX2 (scores pre-scaled by log2e)
            float p0 = ex2(d0);
            float p1 = ex2(d1);
            float p2 = ex2(d2);
            float p3 = ex2(d3);
            l[mt][0] += p0 + p1;
            l[mt][1] += p2 + p3;
            uint32_t P0, P0l, P1, P1l;
            bsplit2(p1, p0, P0, P0l);
            bsplit2(p3, p2, P1, P1l);
            mma1688(O[mt][0][0], O[mt][0][1], O[mt][0][2], O[mt][0][3], P0, P1, vh0,
                    O[mt][0][0], O[mt][0][1], O[mt][0][2], O[mt][0][3]);
            mma1688(O[mt][1][0], O[mt][1][1], O[mt][1][2], O[mt][1][3], P0, P1, vh1,
                    O[mt][1][0], O[mt][1][1], O[mt][1][2], O[mt][1][3]);
            mma1688(O[mt][0][0], O[mt][0][1], O[mt][0][2], O[mt][0][3], P0, P1, vl0,
                    O[mt][0][0], O[mt][0][1], O[mt][0][2], O[mt][0][3]);
            mma1688(O[mt][1][0], O[mt][1][1], O[mt][1][2], O[mt][1][3], P0, P1, vl1,
                    O[mt][1][0], O[mt][1][1], O[mt][1][2], O[mt][1][3]);
            mma1688(O[mt][0][0], O[mt][0][1], O[mt][0][2], O[mt][0][3], P0l, P1l, vh0,
                    O[mt][0][0], O[mt][0][1], O[mt][0][2], O[mt][0][3]);   // P_lo
            mma1688(O[mt][1][0], O[mt][1][1], O[mt][1][2], O[mt][1][3], P0l, P1l, vh1,
                    O[mt][1][0], O[mt][1][1], O[mt][1][2], O[mt][1][3]);   // P_lo
        }
    }

    // ---------------- epilogue: reduce l across t-lanes, write O/l ----------------
    float* ob = g_att + b * (NC * NN) + hh * (ND * NN);
#pragma unroll
    for (int mt = 0; mt < 4; mt++) {
        float l0 = l[mt][0], l1 = l[mt][1];
        l0 += __shfl_xor_sync(0xffffffffu, l0, 1);
        l0 += __shfl_xor_sync(0xffffffffu, l0, 2);
        l1 += __shfl_xor_sync(0xffffffffu, l1, 1);
        l1 += __shfl_xor_sync(0xffffffffu, l1, 2);
        const float inv0 = 1.f / l0;
        const float inv1 = 1.f / l1;
        const int r0 = i0 + (mt << 4) + g;
        const int r1 = r0 + 8;
#pragma unroll
        for (int dn = 0; dn < 2; dn++) {
            const int c0 = dn * 8 + 2 * t;
            ob[c0 * NN + r0]       = O[mt][dn][0] * inv0;
            ob[(c0 + 1) * NN + r0] = O[mt][dn][1] * inv0;
            ob[c0 * NN + r1]       = O[mt][dn][2] * inv1;
            ob[(c0 + 1) * NN + r1] = O[mt][dn][3] * inv1;
        }
    }
}

// =====================================================================
// K3: per-batch reductions (unchanged)
// =====================================================================
__global__ void __launch_bounds__(256)
stats_kernel(const float* __restrict__ x,
             const float* __restrict__ ca_w1, const float* __restrict__ ca_b1,
             const float* __restrict__ ca_w2, const float* __restrict__ ca_b2)
{
    const int b = blockIdx.x, tid = threadIdx.x;
    __shared__ float r1[256], r2[256];
    __shared__ float savg[64], smx2[64], hid[8];

    const float* ab = g_att + b * (NC * NN);
    float s = 0.f, ss = 0.f;
    for (int idx = tid; idx < NC * NN; idx += 256) {
        float v = ab[idx];
        s += v;
        ss += v * v;
    }
    r1[tid] = s; r2[tid] = ss;
    __syncthreads();
    for (int off = 128; off > 0; off >>= 1) {
        if (tid < off) { r1[tid] += r1[tid + off]; r2[tid] += r2[tid + off]; }
        __syncthreads();
    }
    if (tid == 0) {
        float mu  = r1[0] * (1.f / 65536.f);
        float var = r2[0] * (1.f / 65536.f) - mu * mu;
        g_stats[2 * b]     = mu;
        g_stats[2 * b + 1] = rsqrtf(var + 1e-5f);
    }
    __syncthreads();

    {
        int c = tid >> 2, qq = tid & 3;
        const float* xc = x + b * (NC * NN) + c * NN + qq * 256;
        float sa = 0.f, mx = -3.4e38f;
        for (int t2 = 0; t2 < 256; t2++) {
            float v = xc[t2];
            sa += v;
            mx = fmaxf(mx, v);
        }
        r1[tid] = sa; r2[tid] = mx;
    }
    __syncthreads();
    if (tid < 64) {
        float av = 0.f, m = -3.4e38f;
        for (int q2 = 0; q2 < 4; q2++) {
            av += r1[tid * 4 + q2];
            m = fmaxf(m, r2[tid * 4 + q2]);
        }
        savg[tid] = av * (1.f / 1024.f);
        smx2[tid] = m;
    }
    __syncthreads();
    if (tid < 8) {
        int r = tid & 3;
        const float* src = (tid < 4) ? savg : smx2;
        float h = ca_b1[r];
        for (int c2 = 0; c2 < 64; c2++) h += ca_w1[r * 64 + c2] * src[c2];
        hid[tid] = fmaxf(h, 0.f);
    }
    __syncthreads();
    if (tid < 64) {
        float o = 2.f * ca_b2[tid];
        for (int r = 0; r < 4; r++) o += ca_w2[tid * 4 + r] * (hid[r] + hid[4 + r]);
        g_chatt[b * NC + tid] = 1.f / (1.f + __expf(-o));
    }
}

// =====================================================================
// K4a: CBAM spatial map (unchanged)
// =====================================================================
__global__ void __launch_bounds__(1024)
spatial_kernel(const float* __restrict__ x,
               const float* __restrict__ sa_w, const float* __restrict__ sa_b)
{
    const int b = blockIdx.x, tid = threadIdx.x;
    __shared__ float fm[NN], fx[NN], chs[64], wsh[98];
    if (tid < 64) chs[tid] = g_chatt[b * NC + tid];
    if (tid < 98) wsh[tid] = sa_w[tid];
    __syncthreads();

    {
        const float* xb = x + b * (NC * NN) + tid;
        float s = 0.f, m = -3.4e38f;
#pragma unroll
        for (int c = 0; c < 64; c++) {
            float v = chs[c] * xb[c * NN];
            s += v;
            m = fmaxf(m, v);
        }
        fm[tid] = s * (1.f / 64.f);
        fx[tid] = m;
    }
    __syncthreads();

    const int iw = tid >> 5, ih = tid & 31;
    float o = sa_b[0];
#pragma unroll
    for (int ky = 0; ky < 7; ky++) {
        int y = iw + ky - 3;
        if ((unsigned)y < 32u) {
#pragma unroll
            for (int kx = 0; kx < 7; kx++) {
                int xx2 = ih + kx - 3;
                if ((unsigned)xx2 < 32u) {
                    int fi = y * 32 + xx2;
                    o += wsh[ky * 7 + kx] * fm[fi] + wsh[49 + ky * 7 + kx] * fx[fi];
                }
            }
        }
    }
    g_sp[b * NN + tid] = 1.f / (1.f + __expf(-o));
}

// =====================================================================
// K4b: final fuse (unchanged)
// =====================================================================
__global__ void __launch_bounds__(256)
final_kernel(const float* __restrict__ x,
             const float* __restrict__ ln_g, const float* __restrict__ ln_b,
             float* __restrict__ out)
{
    int idx = blockIdx.x * 256 + threadIdx.x;
    int b  = idx >> 16;
    int cn = idx & 65535;
    int c  = cn >> 10;
    int n  = cn & 1023;

    float mu   = g_stats[2 * b];
    float rstd = g_stats[2 * b + 1];
    float xv = x[idx];
    float av = g_att[idx];
    float ln = (av - mu) * rstd * ln_g[cn] + ln_b[cn];
    out[idx] = ln + 2.f * xv + g_sp[b * NN + n] * g_chatt[b * NC + c] * xv;
}

// =====================================================================
extern "C" void kernel_launch(void* const* d_in, const int* in_sizes, int n_in,
                              void* d_out, int out_size)
{
    const float* x     = (const float*)d_in[0];
    const float* Wq    = (const float*)d_in[1];
    const float* bq    = (const float*)d_in[2];
    const float* Wk    = (const float*)d_in[3];
    const float* bk    = (const float*)d_in[4];
    const float* Wv    = (const float*)d_in[5];
    const float* bv    = (const float*)d_in[6];
    const float* rel_h = (const float*)d_in[7];
    const float* rel_w = (const float*)d_in[8];
    const float* ln_g  = (const float*)d_in[9];
    const float* ln_b  = (const float*)d_in[10];
    const float* ca_w1 = (const float*)d_in[11];
    const float* ca_b1 = (const float*)d_in[12];
    const float* ca_w2 = (const float*)d_in[13];
    const float* ca_b2 = (const float*)d_in[14];
    const float* sa_w  = (const float*)d_in[15];
    const float* sa_b  = (const float*)d_in[16];
    float* out = (float*)d_out;

    const int smem1 = (64 * 256 + 3 * 64 * 66) * (int)sizeof(float);
    cudaFuncSetAttribute(qkv_kernel,      cudaFuncAttributeMaxDynamicSharedMemorySize, smem1);
    cudaFuncSetAttribute(attn_mma_kernel, cudaFuncAttributeMaxDynamicSharedMemorySize, SM_TOT2);

    qkv_kernel<<<NB * 4, 512, smem1>>>(x, Wq, bq, Wk, bk, Wv, bv);
    attn_mma_kernel<<<NB * NHEADS, 512, SM_TOT2>>>(rel_h, rel_w);
    stats_kernel<<<NB, 256>>>(x, ca_w1, ca_b1, ca_w2, ca_b2);
    spatial_kernel<<<NB, 1024>>>(x, sa_w, sa_b);
    final_kernel<<<(NB * NC * NN) / 256, 256>>>(x, ln_g, ln_b, out);
}

// round 12
// speedup vs baseline: 2.5284x; 1.2969x over previous
#include <cuda_runtime.h>
#include <cuda_bf16.h>
#include <cuda_fp16.h>
#include <stdint.h>

// Problem constants
#define NB   32
#define NC   64
#define NN   1024
#define NHEADS 4
#define ND   16

typedef unsigned long long ull;

// ---------------- scratch (device globals) ----------------
__device__ float g_q[NB * NC * NN];
__device__ float g_k[NB * NC * NN];
__device__ float g_v[NB * NC * NN];
__device__ float g_att[NB * NC * NN];
__device__ float g_chatt[NB * NC];
__device__ float g_sp[NB * NN];
__device__ float g_stats[NB * 2];

// ---------------- f32x2 helpers (qkv kernel) ----------------
__device__ __forceinline__ ull fma2(ull a, ull b, ull c) {
    ull d;
    asm("fma.rn.f32x2 %0, %1, %2, %3;" : "=l"(d) : "l"(a), "l"(b), "l"(c));
    return d;
}
__device__ __forceinline__ ull pack2(float lo, float hi) {
    ull r;
    asm("mov.b64 %0, {%1, %2};" : "=l"(r) : "f"(lo), "f"(hi));
    return r;
}
__device__ __forceinline__ float2 unpack2(ull v) {
    float2 r;
    asm("mov.b64 {%0, %1}, %2;" : "=f"(r.x), "=f"(r.y) : "l"(v));
    return r;
}
// MUFU exp2
__device__ __forceinline__ float ex2(float x) {
    float r;
    asm("ex2.approx.ftz.f32 %0, %1;" : "=f"(r) : "f"(x));
    return r;
}
// fp16x2 pack (hi -> upper, lo -> lower)
__device__ __forceinline__ uint32_t hpack(float hi, float lo) {
    uint32_t r;
    asm("cvt.rn.f16x2.f32 %0, %1, %2;" : "=r"(r) : "f"(hi), "f"(lo));
    return r;
}
// saturating pack for P (clamps to 65504 instead of inf)
__device__ __forceinline__ uint32_t hpacks(float hi, float lo) {
    uint32_t r;
    asm("cvt.rn.satfinite.f16x2.f32 %0, %1, %2;" : "=r"(r) : "f"(hi), "f"(lo));
    return r;
}
__device__ __forceinline__ float2 h22f2(uint32_t v) {
    __half2 h = *reinterpret_cast<__half2*>(&v);
    return __half22float2(h);
}

// =====================================================================
// K1: QKV projection (validated)
// =====================================================================
__global__ void __launch_bounds__(512, 1)
qkv_kernel(const float* __restrict__ x,
           const float* __restrict__ Wq, const float* __restrict__ bq,
           const float* __restrict__ Wk, const float* __restrict__ bk,
           const float* __restrict__ Wv, const float* __restrict__ bv)
{
    extern __shared__ float sm1[];
    float* xs = sm1;
    float* ws = sm1 + 64 * 256;

    const int b  = blockIdx.x >> 2;
    const int n0 = (blockIdx.x & 3) << 8;
    const int tid = threadIdx.x;

    const float* xb = x + b * (NC * NN);
    for (int idx = tid; idx < 64 * 256; idx += 512) {
        int c = idx >> 8, nl = idx & 255;
        xs[idx] = xb[c * NN + n0 + nl];
    }
    {
        const float* wsrc[3] = {Wq, Wk, Wv};
        for (int m = 0; m < 3; m++) {
            const float* w = wsrc[m];
            for (int idx = tid; idx < 4096; idx += 512) {
                int o = idx >> 6, c = idx & 63;
                ws[m * 4224 + c * 66 + o] = w[idx];
            }
        }
    }
    __syncthreads();

    const int nl = (tid & 127) << 1;
    const int og = (tid >> 7) << 4;

    ull acc[3][8][2];
    {
        const float* bias[3] = {bq, bk, bv};
#pragma unroll
        for (int m = 0; m < 3; m++)
#pragma unroll
            for (int p = 0; p < 8; p++) {
                ull bb = pack2(bias[m][og + 2 * p], bias[m][og + 2 * p + 1]);
                acc[m][p][0] = bb;
                acc[m][p][1] = bb;
            }
    }

#pragma unroll 4
    for (int c = 0; c < 64; c++) {
        float xv0 = xs[c * 256 + nl];
        float xv1 = xs[c * 256 + nl + 1];
        ull x0 = pack2(xv0, xv0);
        ull x1 = pack2(xv1, xv1);
#pragma unroll
        for (int m = 0; m < 3; m++) {
            const ull* wrow = (const ull*)&ws[m * 4224 + c * 66 + og];
#pragma unroll
            for (int p = 0; p < 8; p++) {
                ull w2 = wrow[p];
                acc[m][p][0] = fma2(x0, w2, acc[m][p][0]);
                acc[m][p][1] = fma2(x1, w2, acc[m][p][1]);
            }
        }
    }

    {
        float* dsts[3] = {g_q, g_k, g_v};
#pragma unroll
        for (int m = 0; m < 3; m++) {
            float* dst = dsts[m] + b * (NC * NN);
#pragma unroll
            for (int p = 0; p < 8; p++) {
                float2 a0 = unpack2(acc[m][p][0]);
                float2 a1 = unpack2(acc[m][p][1]);
                int o = og + 2 * p;
                *(float2*)&dst[o * NN + n0 + nl]       = make_float2(a0.x, a1.x);
                *(float2*)&dst[(o + 1) * NN + n0 + nl] = make_float2(a0.y, a1.y);
            }
        }
    }
}

// =====================================================================
// fp16 mma.sync helpers
// =====================================================================
// c01 -> rows r0 (c0,c1), c23 -> rows r1 (c2,c3): per-row softmax bias.
__device__ __forceinline__ void mmaS16(float& d0, float& d1, float& d2, float& d3,
    uint32_t a0, uint32_t a1, uint32_t a2, uint32_t a3,
    uint32_t b0, uint32_t b1, float c01, float c23)
{
    asm("mma.sync.aligned.m16n8k16.row.col.f32.f16.f16.f32 "
        "{%0,%1,%2,%3}, {%4,%5,%6,%7}, {%8,%9}, {%10,%10,%11,%11};"
        : "=f"(d0), "=f"(d1), "=f"(d2), "=f"(d3)
        : "r"(a0), "r"(a1), "r"(a2), "r"(a3), "r"(b0), "r"(b1),
          "f"(c01), "f"(c23));
}
__device__ __forceinline__ void mmaPV(float* O,
    uint32_t a0, uint32_t a1, uint32_t b0)
{
    asm("mma.sync.aligned.m16n8k8.row.col.f32.f16.f16.f32 "
        "{%0,%1,%2,%3}, {%4,%5}, {%6}, {%0,%1,%2,%3};"
        : "+f"(O[0]), "+f"(O[1]), "+f"(O[2]), "+f"(O[3])
        : "r"(a0), "r"(a1), "r"(b0));
}

// smem layout (bytes)
#define SM2_K    0            // K fp16: 1024 rows x 32B, XOR16 swizzle  (32768)
#define SM2_V    32768        // V fp16: 16 rows x 2064B                 (33024)
#define SM2_CH   65792        // ch table fp16: 32 rows x 2064B          (66048)
#define SM2_CW   131840       // cw table fp16: 32 rows x 2064B          (66048)
#define SM2_RH   197888       // rel_h staged fp32 16x32 / later: partial maxes
#define SM2_RW   199936       // rel_w staged fp32 16x32 / later: row maxes MM[64]
#define SM2_TOT  201984

// =====================================================================
// K2: flash attention, fp16 mma.sync + positional-score tables + row bias.
// 1 CTA per (b,head), 512 threads.
// S' = q.k*L2E - bias_row (1 MMA, bias in C frag) ; + ch[ih,j] + cw[iw,j]
// P' = exp2(S') fp16 (satfinite) ; O += P' x V (2 MMAs) ; O/l cancels bias.
// =====================================================================
__global__ void __launch_bounds__(512, 1)
attn_fa_kernel(const float* __restrict__ rel_h, const float* __restrict__ rel_w)
{
    extern __shared__ char sm[];
    const int tid  = threadIdx.x;
    const int warp = tid >> 5;
    const int lane = tid & 31;
    const int g = lane >> 2;
    const int t = lane & 3;
    const int b  = blockIdx.x >> 2;
    const int hh = blockIdx.x & 3;

    const float* qb = g_q + b * (NC * NN) + hh * (ND * NN);
    const float* kb = g_k + b * (NC * NN) + hh * (ND * NN);
    const float* vb = g_v + b * (NC * NN) + hh * (ND * NN);
    const float L2E = 1.4426950408889634f;

    float* RH = (float*)(sm + SM2_RH);
    float* RW = (float*)(sm + SM2_RW);

    // ---- stage rel (x L2E): 512 threads = 16 d x 32 pos ----
    {
        int d = tid >> 5, ip = tid & 31;
        RH[tid] = rel_h[(hh * ND + d) * 32 + ip] * L2E;
        RW[tid] = rel_w[(hh * ND + d) * 32 + ip] * L2E;
    }

    // ---- fill K fp16 (swizzled) ----
#pragma unroll
    for (int rep = 0; rep < 2; rep++) {
        const int j = tid + (rep << 9);
        char* base = sm + SM2_K + j * 32;
        const uint32_t xo = (uint32_t)((j & 4) << 2);
#pragma unroll
        for (int p = 0; p < 8; p++) {
            uint32_t v = hpack(kb[(2 * p + 1) * NN + j], kb[2 * p * NN + j]);
            *(uint32_t*)(base + ((uint32_t)(4 * p) ^ xo)) = v;
        }
    }
    // ---- fill V fp16 ----
    {
        const int jp = tid << 1;
#pragma unroll
        for (int d = 0; d < 16; d++) {
            *(uint32_t*)(sm + SM2_V + d * 2064 + tid * 4) =
                hpack(vb[d * NN + jp + 1], vb[d * NN + jp]);
        }
    }
    __syncthreads();   // #1: RH/RW, K, V ready

    // ---- compute ch/cw tables (fp16) ----
#pragma unroll
    for (int rep = 0; rep < 2; rep++) {
        const int j = tid + (rep << 9);
        float qj[16];
#pragma unroll
        for (int d = 0; d < 16; d++) qj[d] = qb[d * NN + j];
        for (int ih = 0; ih < 32; ih++) {
            float sh = 0.f, sw = 0.f;
#pragma unroll
            for (int d = 0; d < 16; d++) {
                sh += RH[d * 32 + ih] * qj[d];
                sw += RW[d * 32 + ih] * qj[d];
            }
            *(__half*)(sm + SM2_CH + ih * 2064 + 2 * j) = __float2half_rn(sh);
            *(__half*)(sm + SM2_CW + ih * 2064 + 2 * j) = __float2half_rn(sw);
        }
    }
    __syncthreads();   // #2: tables ready; RH/RW regions now reusable

    // ---- row maxima of tables (overflow guard): PM in RH region ----
    {
        const int row = tid >> 3, seg = tid & 7;      // 64 rows x 8 segs
        const char* tb = (row < 32) ? (sm + SM2_CH + row * 2064)
                                    : (sm + SM2_CW + (row - 32) * 2064);
        const uint32_t* p32 = (const uint32_t*)(tb + seg * 256);
        float mx = -1e30f;
#pragma unroll 8
        for (int jj = 0; jj < 64; jj++) {
            float2 v = h22f2(p32[jj]);
            mx = fmaxf(mx, fmaxf(v.x, v.y));
        }
        RH[tid] = mx;    // PM[row*8+seg]
    }
    __syncthreads();   // #3
    float* MM = RW;    // MM[0..31] = M_h, MM[32..63] = M_w
    if (tid < 64) {
        const float* pm = RH + tid * 8;
        float m = pm[0];
#pragma unroll
        for (int s2 = 1; s2 < 8; s2++) m = fmaxf(m, pm[s2]);
        MM[tid] = m;
    }
    __syncthreads();   // #4: MM ready

    // ---- build A fragments: (L2E * q) fp16, 4 m-tiles + row biases ----
    const int i0 = warp << 6;
    uint32_t fa[4][4];
    float nbA[4], nbB[4];
#pragma unroll
    for (int mt = 0; mt < 4; mt++) {
        const int r0 = i0 + (mt << 4) + g;
        const int r1 = r0 + 8;
#pragma unroll
        for (int half = 0; half < 2; half++) {
            const int dA = 2 * t + half * 8;
            fa[mt][half * 2 + 0] = hpack(qb[(dA + 1) * NN + r0] * L2E,
                                         qb[dA * NN + r0] * L2E);
            fa[mt][half * 2 + 1] = hpack(qb[(dA + 1) * NN + r1] * L2E,
                                         qb[dA * NN + r1] * L2E);
        }
        const int ihA = ((mt & 1) << 4) + g;
        const int iw  = 2 * warp + (mt >> 1);
        const float mw = MM[32 + iw];
        nbA[mt] = -(MM[ihA] + mw + 2.0f);
        nbB[mt] = -(MM[ihA + 8] + mw + 2.0f);
    }

    // ---- mainloop ----
    float O[4][2][4];
    float l[4][2];
#pragma unroll
    for (int mt = 0; mt < 4; mt++) {
#pragma unroll
        for (int dn = 0; dn < 2; dn++)
#pragma unroll
            for (int r = 0; r < 4; r++) O[mt][dn][r] = 0.f;
        l[mt][0] = 0.f; l[mt][1] = 0.f;
    }

    const uint32_t koff0 = ((uint32_t)(4 * t))      ^ (uint32_t)((g & 4) << 2);
    const uint32_t koff1 = ((uint32_t)(16 + 4 * t)) ^ (uint32_t)((g & 4) << 2);
    const char* kbase  = sm + SM2_K + g * 32;
    const char* vbase0 = sm + SM2_V + g * 2064 + t * 4;
    const char* vbase1 = sm + SM2_V + (8 + g) * 2064 + t * 4;
    const char* chb0 = sm + SM2_CH + g * 2064 + t * 4;          // mt even, r0
    const char* chb1 = sm + SM2_CH + (g + 8) * 2064 + t * 4;    // mt even, r1
    const char* chb2 = sm + SM2_CH + (16 + g) * 2064 + t * 4;   // mt odd, r0
    const char* chb3 = sm + SM2_CH + (24 + g) * 2064 + t * 4;   // mt odd, r1
    const char* cwb0 = sm + SM2_CW + (2 * warp) * 2064 + t * 4;       // mt 0,1
    const char* cwb1 = sm + SM2_CW + (2 * warp + 1) * 2064 + t * 4;   // mt 2,3

    for (int j8 = 0; j8 < 128; j8++) {
        const uint32_t jb32 = (uint32_t)j8 << 8;   // j0 * 32
        const uint32_t jb2  = (uint32_t)j8 << 4;   // j0 * 2
        const uint32_t kb0 = *(const uint32_t*)(kbase + jb32 + koff0);
        const uint32_t kb1 = *(const uint32_t*)(kbase + jb32 + koff1);
        const uint32_t vb0 = *(const uint32_t*)(vbase0 + jb2);
        const uint32_t vb1 = *(const uint32_t*)(vbase1 + jb2);
        const float2 cw0 = h22f2(*(const uint32_t*)(cwb0 + jb2));
        const float2 cw1 = h22f2(*(const uint32_t*)(cwb1 + jb2));
        const float2 ch0 = h22f2(*(const uint32_t*)(chb0 + jb2));
        const float2 ch1 = h22f2(*(const uint32_t*)(chb1 + jb2));
        const float2 ch2 = h22f2(*(const uint32_t*)(chb2 + jb2));
        const float2 ch3 = h22f2(*(const uint32_t*)(chb3 + jb2));

#pragma unroll
        for (int mt = 0; mt < 4; mt++) {
            const float2 cA = (mt & 1) ? ch2 : ch0;
            const float2 cB = (mt & 1) ? ch3 : ch1;
            const float2 cw = (mt & 2) ? cw1 : cw0;
            float d0, d1, d2, d3;
            mmaS16(d0, d1, d2, d3, fa[mt][0], fa[mt][1], fa[mt][2], fa[mt][3],
                   kb0, kb1, nbA[mt], nbB[mt]);
            float p0 = ex2(d0 + cA.x + cw.x);
            float p1 = ex2(d1 + cA.y + cw.y);
            float p2 = ex2(d2 + cB.x + cw.x);
            float p3 = ex2(d3 + cB.y + cw.y);
            l[mt][0] += p0 + p1;
            l[mt][1] += p2 + p3;
            const uint32_t P0 = hpacks(p1, p0);
            const uint32_t P1 = hpacks(p3, p2);
            mmaPV(O[mt][0], P0, P1, vb0);
            mmaPV(O[mt][1], P0, P1, vb1);
        }
    }

    // ---- epilogue ----
    float* ob = g_att + b * (NC * NN) + hh * (ND * NN);
#pragma unroll
    for (int mt = 0; mt < 4; mt++) {
        float l0 = l[mt][0], l1 = l[mt][1];
        l0 += __shfl_xor_sync(0xffffffffu, l0, 1);
        l0 += __shfl_xor_sync(0xffffffffu, l0, 2);
        l1 += __shfl_xor_sync(0xffffffffu, l1, 1);
        l1 += __shfl_xor_sync(0xffffffffu, l1, 2);
        const float inv0 = 1.f / l0;
        const float inv1 = 1.f / l1;
        const int r0 = i0 + (mt << 4) + g;
        const int r1 = r0 + 8;
#pragma unroll
        for (int dn = 0; dn < 2; dn++) {
            const int c0 = dn * 8 + 2 * t;
            ob[c0 * NN + r0]       = O[mt][dn][0] * inv0;
            ob[(c0 + 1) * NN + r0] = O[mt][dn][1] * inv0;
            ob[c0 * NN + r1]       = O[mt][dn][2] * inv1;
            ob[(c0 + 1) * NN + r1] = O[mt][dn][3] * inv1;
        }
    }
}

// =====================================================================
// K3: per-batch reductions (unchanged)
// =====================================================================
__global__ void __launch_bounds__(256)
stats_kernel(const float* __restrict__ x,
             const float* __restrict__ ca_w1, const float* __restrict__ ca_b1,
             const float* __restrict__ ca_w2, const float* __restrict__ ca_b2)
{
    const int b = blockIdx.x, tid = threadIdx.x;
    __shared__ float r1[256], r2[256];
    __shared__ float savg[64], smx2[64], hid[8];

    const float* ab = g_att + b * (NC * NN);
    float s = 0.f, ss = 0.f;
    for (int idx = tid; idx < NC * NN; idx += 256) {
        float v = ab[idx];
        s += v;
        ss += v * v;
    }
    r1[tid] = s; r2[tid] = ss;
    __syncthreads();
    for (int off = 128; off > 0; off >>= 1) {
        if (tid < off) { r1[tid] += r1[tid + off]; r2[tid] += r2[tid + off]; }
        __syncthreads();
    }
    if (tid == 0) {
        float mu  = r1[0] * (1.f / 65536.f);
        float var = r2[0] * (1.f / 65536.f) - mu * mu;
        g_stats[2 * b]     = mu;
        g_stats[2 * b + 1] = rsqrtf(var + 1e-5f);
    }
    __syncthreads();

    {
        int c = tid >> 2, qq = tid & 3;
        const float* xc = x + b * (NC * NN) + c * NN + qq * 256;
        float sa = 0.f, mx = -3.4e38f;
        for (int t2 = 0; t2 < 256; t2++) {
            float v = xc[t2];
            sa += v;
            mx = fmaxf(mx, v);
        }
        r1[tid] = sa; r2[tid] = mx;
    }
    __syncthreads();
    if (tid < 64) {
        float av = 0.f, m = -3.4e38f;
        for (int q2 = 0; q2 < 4; q2++) {
            av += r1[tid * 4 + q2];
            m = fmaxf(m, r2[tid * 4 + q2]);
        }
        savg[tid] = av * (1.f / 1024.f);
        smx2[tid] = m;
    }
    __syncthreads();
    if (tid < 8) {
        int r = tid & 3;
        const float* src = (tid < 4) ? savg : smx2;
        float h = ca_b1[r];
        for (int c2 = 0; c2 < 64; c2++) h += ca_w1[r * 64 + c2] * src[c2];
        hid[tid] = fmaxf(h, 0.f);
    }
    __syncthreads();
    if (tid < 64) {
        float o = 2.f * ca_b2[tid];
        for (int r = 0; r < 4; r++) o += ca_w2[tid * 4 + r] * (hid[r] + hid[4 + r]);
        g_chatt[b * NC + tid] = 1.f / (1.f + __expf(-o));
    }
}

// =====================================================================
// K4a: CBAM spatial map — 4 CTAs per batch
// =====================================================================
__global__ void __launch_bounds__(1024)
spatial_kernel(const float* __restrict__ x,
               const float* __restrict__ sa_w, const float* __restrict__ sa_b)
{
    const int b = blockIdx.x >> 2, qd = blockIdx.x & 3, tid = threadIdx.x;
    __shared__ float fm[NN], fx[NN], chs[64], wsh[98];
    if (tid < 64) chs[tid] = g_chatt[b * NC + tid];
    if (tid < 98) wsh[tid] = sa_w[tid];
    __syncthreads();

    {
        const float* xb = x + b * (NC * NN) + tid;
        float s = 0.f, m = -3.4e38f;
#pragma unroll
        for (int c = 0; c < 64; c++) {
            float v = chs[c] * xb[c * NN];
            s += v;
            m = fmaxf(m, v);
        }
        fm[tid] = s * (1.f / 64.f);
        fx[tid] = m;
    }
    __syncthreads();

    if (tid < 256) {
        const int iw = (qd << 3) + (tid >> 5), ih = tid & 31;
        float o = sa_b[0];
#pragma unroll
        for (int ky = 0; ky < 7; ky++) {
            int y = iw + ky - 3;
            if ((unsigned)y < 32u) {
#pragma unroll
                for (int kx = 0; kx < 7; kx++) {
                    int xx2 = ih + kx - 3;
                    if ((unsigned)xx2 < 32u) {
                        int fi = y * 32 + xx2;
                        o += wsh[ky * 7 + kx] * fm[fi] + wsh[49 + ky * 7 + kx] * fx[fi];
                    }
                }
            }
        }
        g_sp[b * NN + iw * 32 + ih] = 1.f / (1.f + __expf(-o));
    }
}

// =====================================================================
// K4b: final fuse (unchanged)
// =====================================================================
__global__ void __launch_bounds__(256)
final_kernel(const float* __restrict__ x,
             const float* __restrict__ ln_g, const float* __restrict__ ln_b,
             float* __restrict__ out)
{
    int idx = blockIdx.x * 256 + threadIdx.x;
    int b  = idx >> 16;
    int cn = idx & 65535;
    int c  = cn >> 10;
    int n  = cn & 1023;

    float mu   = g_stats[2 * b];
    float rstd = g_stats[2 * b + 1];
    float xv = x[idx];
    float av = g_att[idx];
    float ln = (av - mu) * rstd * ln_g[cn] + ln_b[cn];
    out[idx] = ln + 2.f * xv + g_sp[b * NN + n] * g_chatt[b * NC + c] * xv;
}

// =====================================================================
extern "C" void kernel_launch(void* const* d_in, const int* in_sizes, int n_in,
                              void* d_out, int out_size)
{
    const float* x     = (const float*)d_in[0];
    const float* Wq    = (const float*)d_in[1];
    const float* bq    = (const float*)d_in[2];
    const float* Wk    = (const float*)d_in[3];
    const float* bk    = (const float*)d_in[4];
    const float* Wv    = (const float*)d_in[5];
    const float* bv    = (const float*)d_in[6];
    const float* rel_h = (const float*)d_in[7];
    const float* rel_w = (const float*)d_in[8];
    const float* ln_g  = (const float*)d_in[9];
    const float* ln_b  = (const float*)d_in[10];
    const float* ca_w1 = (const float*)d_in[11];
    const float* ca_b1 = (const float*)d_in[12];
    const float* ca_w2 = (const float*)d_in[13];
    const float* ca_b2 = (const float*)d_in[14];
    const float* sa_w  = (const float*)d_in[15];
    const float* sa_b  = (const float*)d_in[16];
    float* out = (float*)d_out;

    const int smem1 = (64 * 256 + 3 * 64 * 66) * (int)sizeof(float);
    cudaFuncSetAttribute(qkv_kernel,     cudaFuncAttributeMaxDynamicSharedMemorySize, smem1);
    cudaFuncSetAttribute(attn_fa_kernel, cudaFuncAttributeMaxDynamicSharedMemorySize, SM2_TOT);

    qkv_kernel<<<NB * 4, 512, smem1>>>(x, Wq, bq, Wk, bk, Wv, bv);
    attn_fa_kernel<<<NB * NHEADS, 512, SM2_TOT>>>(rel_h, rel_w);
    stats_kernel<<<NB, 256>>>(x, ca_w1, ca_b1, ca_w2, ca_b2);
    spatial_kernel<<<NB * 4, 1024>>>(x, sa_w, sa_b);
    final_kernel<<<(NB * NC * NN) / 256, 256>>>(x, ln_g, ln_b, out);
}

// round 16
// speedup vs baseline: 2.5361x; 1.0030x over previous
#include <cuda_runtime.h>
#include <cuda_bf16.h>
#include <cuda_fp16.h>
#include <stdint.h>

// Problem constants
#define NB   32
#define NC   64
#define NN   1024
#define NHEADS 4
#define ND   16

typedef unsigned long long ull;

// ---------------- scratch (device globals) ----------------
__device__ float g_q[NB * NC * NN];
__device__ float g_k[NB * NC * NN];
__device__ float g_v[NB * NC * NN];
__device__ float g_att[NB * NC * NN];
__device__ float g_chatt[NB * NC];
__device__ float g_sp[NB * NN];
__device__ float g_lnpart[NB * NHEADS * 2];   // per-(b,head) LN partial (s, ss)

// ---------------- f32x2 helpers (qkv kernel) ----------------
__device__ __forceinline__ ull fma2(ull a, ull b, ull c) {
    ull d;
    asm("fma.rn.f32x2 %0, %1, %2, %3;" : "=l"(d) : "l"(a), "l"(b), "l"(c));
    return d;
}
__device__ __forceinline__ ull pack2(float lo, float hi) {
    ull r;
    asm("mov.b64 %0, {%1, %2};" : "=l"(r) : "f"(lo), "f"(hi));
    return r;
}
__device__ __forceinline__ float2 unpack2(ull v) {
    float2 r;
    asm("mov.b64 {%0, %1}, %2;" : "=f"(r.x), "=f"(r.y) : "l"(v));
    return r;
}
// MUFU exp2 (fp32 — the accuracy-validated path)
__device__ __forceinline__ float ex2(float x) {
    float r;
    asm("ex2.approx.ftz.f32 %0, %1;" : "=f"(r) : "f"(x));
    return r;
}
// fp16x2 pack (hi -> upper, lo -> lower)
__device__ __forceinline__ uint32_t hpack(float hi, float lo) {
    uint32_t r;
    asm("cvt.rn.f16x2.f32 %0, %1, %2;" : "=r"(r) : "f"(hi), "f"(lo));
    return r;
}
// saturating pack for P (clamps to 65504 instead of inf)
__device__ __forceinline__ uint32_t hpacks(float hi, float lo) {
    uint32_t r;
    asm("cvt.rn.satfinite.f16x2.f32 %0, %1, %2;" : "=r"(r) : "f"(hi), "f"(lo));
    return r;
}
__device__ __forceinline__ float2 h22f2(uint32_t v) {
    __half2 h = *reinterpret_cast<__half2*>(&v);
    return __half22float2(h);
}

#define ONES_H2 0x3C003C00u   // fp16x2 (1.0, 1.0)

// =====================================================================
// K1: QKV projection (validated)
// =====================================================================
__global__ void __launch_bounds__(512, 1)
qkv_kernel(const float* __restrict__ x,
           const float* __restrict__ Wq, const float* __restrict__ bq,
           const float* __restrict__ Wk, const float* __restrict__ bk,
           const float* __restrict__ Wv, const float* __restrict__ bv)
{
    extern __shared__ float sm1[];
    float* xs = sm1;
    float* ws = sm1 + 64 * 256;

    const int b  = blockIdx.x >> 2;
    const int n0 = (blockIdx.x & 3) << 8;
    const int tid = threadIdx.x;

    const float* xb = x + b * (NC * NN);
    for (int idx = tid; idx < 64 * 256; idx += 512) {
        int c = idx >> 8, nl = idx & 255;
        xs[idx] = xb[c * NN + n0 + nl];
    }
    {
        const float* wsrc[3] = {Wq, Wk, Wv};
        for (int m = 0; m < 3; m++) {
            const float* w = wsrc[m];
            for (int idx = tid; idx < 4096; idx += 512) {
                int o = idx >> 6, c = idx & 63;
                ws[m * 4224 + c * 66 + o] = w[idx];
            }
        }
    }
    __syncthreads();

    const int nl = (tid & 127) << 1;
    const int og = (tid >> 7) << 4;

    ull acc[3][8][2];
    {
        const float* bias[3] = {bq, bk, bv};
#pragma unroll
        for (int m = 0; m < 3; m++)
#pragma unroll
            for (int p = 0; p < 8; p++) {
                ull bb = pack2(bias[m][og + 2 * p], bias[m][og + 2 * p + 1]);
                acc[m][p][0] = bb;
                acc[m][p][1] = bb;
            }
    }

#pragma unroll 4
    for (int c = 0; c < 64; c++) {
        float xv0 = xs[c * 256 + nl];
        float xv1 = xs[c * 256 + nl + 1];
        ull x0 = pack2(xv0, xv0);
        ull x1 = pack2(xv1, xv1);
#pragma unroll
        for (int m = 0; m < 3; m++) {
            const ull* wrow = (const ull*)&ws[m * 4224 + c * 66 + og];
#pragma unroll
            for (int p = 0; p < 8; p++) {
                ull w2 = wrow[p];
                acc[m][p][0] = fma2(x0, w2, acc[m][p][0]);
                acc[m][p][1] = fma2(x1, w2, acc[m][p][1]);
            }
        }
    }

    {
        float* dsts[3] = {g_q, g_k, g_v};
#pragma unroll
        for (int m = 0; m < 3; m++) {
            float* dst = dsts[m] + b * (NC * NN);
#pragma unroll
            for (int p = 0; p < 8; p++) {
                float2 a0 = unpack2(acc[m][p][0]);
                float2 a1 = unpack2(acc[m][p][1]);
                int o = og + 2 * p;
                *(float2*)&dst[o * NN + n0 + nl]       = make_float2(a0.x, a1.x);
                *(float2*)&dst[(o + 1) * NN + n0 + nl] = make_float2(a0.y, a1.y);
            }
        }
    }
}

// =====================================================================
// fp16 mma.sync helpers
// =====================================================================
__device__ __forceinline__ void mmaS16(float& d0, float& d1, float& d2, float& d3,
    uint32_t a0, uint32_t a1, uint32_t a2, uint32_t a3,
    uint32_t b0, uint32_t b1, float c01, float c23)
{
    asm("mma.sync.aligned.m16n8k16.row.col.f32.f16.f16.f32 "
        "{%0,%1,%2,%3}, {%4,%5,%6,%7}, {%8,%9}, {%10,%10,%11,%11};"
        : "=f"(d0), "=f"(d1), "=f"(d2), "=f"(d3)
        : "r"(a0), "r"(a1), "r"(a2), "r"(a3), "r"(b0), "r"(b1),
          "f"(c01), "f"(c23));
}
__device__ __forceinline__ void mmaPV(float* O,
    uint32_t a0, uint32_t a1, uint32_t b0)
{
    asm("mma.sync.aligned.m16n8k8.row.col.f32.f16.f16.f32 "
        "{%0,%1,%2,%3}, {%4,%5}, {%6}, {%0,%1,%2,%3};"
        : "+f"(O[0]), "+f"(O[1]), "+f"(O[2]), "+f"(O[3])
        : "r"(a0), "r"(a1), "r"(b0));
}

// smem layout (bytes)
#define SM2_K    0            // K fp16: 1024 rows x 32B, XOR16 swizzle  (32768)
#define SM2_V    32768        // V fp16: 16 rows x 2064B                 (33024)
#define SM2_CH   65792        // ch table fp16: 32 rows x 2064B          (66048)
#define SM2_CW   131840       // cw table fp16: 32 rows x 2064B          (66048)
#define SM2_RH   197888       // rel_h staged fp32 / partial maxes / LN reduce
#define SM2_RW   199936       // rel_w staged fp32 / row maxes MM[64]
#define SM2_TOT  201984

// =====================================================================
// K2: flash attention. fp32 score math + fp32 MUFU exp (R12-validated),
// P fp16 satfinite; l via ones-column MMA; LN partials fused.
// =====================================================================
__global__ void __launch_bounds__(512, 1)
attn_fa_kernel(const float* __restrict__ rel_h, const float* __restrict__ rel_w)
{
    extern __shared__ char sm[];
    const int tid  = threadIdx.x;
    const int warp = tid >> 5;
    const int lane = tid & 31;
    const int g = lane >> 2;
    const int t = lane & 3;
    const int b  = blockIdx.x >> 2;
    const int hh = blockIdx.x & 3;

    const float* qb = g_q + b * (NC * NN) + hh * (ND * NN);
    const float* kb = g_k + b * (NC * NN) + hh * (ND * NN);
    const float* vb = g_v + b * (NC * NN) + hh * (ND * NN);
    const float L2E = 1.4426950408889634f;

    float* RH = (float*)(sm + SM2_RH);
    float* RW = (float*)(sm + SM2_RW);

    // ---- stage rel (x L2E): 512 threads = 16 d x 32 pos ----
    {
        int d = tid >> 5, ip = tid & 31;
        RH[tid] = rel_h[(hh * ND + d) * 32 + ip] * L2E;
        RW[tid] = rel_w[(hh * ND + d) * 32 + ip] * L2E;
    }

    // ---- fill K fp16 (swizzled) ----
#pragma unroll
    for (int rep = 0; rep < 2; rep++) {
        const int j = tid + (rep << 9);
        char* base = sm + SM2_K + j * 32;
        const uint32_t xo = (uint32_t)((j & 4) << 2);
#pragma unroll
        for (int p = 0; p < 8; p++) {
            uint32_t v = hpack(kb[(2 * p + 1) * NN + j], kb[2 * p * NN + j]);
            *(uint32_t*)(base + ((uint32_t)(4 * p) ^ xo)) = v;
        }
    }
    // ---- fill V fp16 ----
    {
        const int jp = tid << 1;
#pragma unroll
        for (int d = 0; d < 16; d++) {
            *(uint32_t*)(sm + SM2_V + d * 2064 + tid * 4) =
                hpack(vb[d * NN + jp + 1], vb[d * NN + jp]);
        }
    }
    __syncthreads();   // #1

    // ---- compute ch/cw tables (fp16) ----
#pragma unroll
    for (int rep = 0; rep < 2; rep++) {
        const int j = tid + (rep << 9);
        float qj[16];
#pragma unroll
        for (int d = 0; d < 16; d++) qj[d] = qb[d * NN + j];
        for (int ih = 0; ih < 32; ih++) {
            float sh = 0.f, sw = 0.f;
#pragma unroll
            for (int d = 0; d < 16; d++) {
                sh += RH[d * 32 + ih] * qj[d];
                sw += RW[d * 32 + ih] * qj[d];
            }
            *(__half*)(sm + SM2_CH + ih * 2064 + 2 * j) = __float2half_rn(sh);
            *(__half*)(sm + SM2_CW + ih * 2064 + 2 * j) = __float2half_rn(sw);
        }
    }
    __syncthreads();   // #2

    // ---- row maxima of tables (overflow guard) ----
    {
        const int row = tid >> 3, seg = tid & 7;
        const char* tb = (row < 32) ? (sm + SM2_CH + row * 2064)
                                    : (sm + SM2_CW + (row - 32) * 2064);
        const uint32_t* p32 = (const uint32_t*)(tb + seg * 256);
        float mx = -1e30f;
#pragma unroll 8
        for (int jj = 0; jj < 64; jj++) {
            float2 v = h22f2(p32[jj]);
            mx = fmaxf(mx, fmaxf(v.x, v.y));
        }
        RH[tid] = mx;
    }
    __syncthreads();   // #3
    float* MM = RW;
    if (tid < 64) {
        const float* pm = RH + tid * 8;
        float m = pm[0];
#pragma unroll
        for (int s2 = 1; s2 < 8; s2++) m = fmaxf(m, pm[s2]);
        MM[tid] = m;
    }
    __syncthreads();   // #4

    // ---- build A fragments + row biases ----
    const int i0 = warp << 6;
    uint32_t fa[4][4];
    float nbA[4], nbB[4];
#pragma unroll
    for (int mt = 0; mt < 4; mt++) {
        const int r0 = i0 + (mt << 4) + g;
        const int r1 = r0 + 8;
#pragma unroll
        for (int half = 0; half < 2; half++) {
            const int dA = 2 * t + half * 8;
            fa[mt][half * 2 + 0] = hpack(qb[(dA + 1) * NN + r0] * L2E,
                                         qb[dA * NN + r0] * L2E);
            fa[mt][half * 2 + 1] = hpack(qb[(dA + 1) * NN + r1] * L2E,
                                         qb[dA * NN + r1] * L2E);
        }
        const int ihA = ((mt & 1) << 4) + g;
        const int iw  = 2 * warp + (mt >> 1);
        const float mw = MM[32 + iw];
        nbA[mt] = -(MM[ihA] + mw + 2.0f);
        nbB[mt] = -(MM[ihA + 8] + mw + 2.0f);
    }

    // ---- mainloop ----
    float O[4][2][4];
    float L[4][4];     // ones-MMA accumulators: L[mt][0]=l(r0), L[mt][2]=l(r1)
#pragma unroll
    for (int mt = 0; mt < 4; mt++) {
#pragma unroll
        for (int dn = 0; dn < 2; dn++)
#pragma unroll
            for (int r = 0; r < 4; r++) O[mt][dn][r] = 0.f;
#pragma unroll
        for (int r = 0; r < 4; r++) L[mt][r] = 0.f;
    }

    const uint32_t koff0 = ((uint32_t)(4 * t))      ^ (uint32_t)((g & 4) << 2);
    const uint32_t koff1 = ((uint32_t)(16 + 4 * t)) ^ (uint32_t)((g & 4) << 2);
    const char* kbase  = sm + SM2_K + g * 32;
    const char* vbase0 = sm + SM2_V + g * 2064 + t * 4;
    const char* vbase1 = sm + SM2_V + (8 + g) * 2064 + t * 4;
    const char* chb0 = sm + SM2_CH + g * 2064 + t * 4;          // mt even, r0
    const char* chb1 = sm + SM2_CH + (g + 8) * 2064 + t * 4;    // mt even, r1
    const char* chb2 = sm + SM2_CH + (16 + g) * 2064 + t * 4;   // mt odd, r0
    const char* chb3 = sm + SM2_CH + (24 + g) * 2064 + t * 4;   // mt odd, r1
    const char* cwb0 = sm + SM2_CW + (2 * warp) * 2064 + t * 4;       // mt 0,1
    const char* cwb1 = sm + SM2_CW + (2 * warp + 1) * 2064 + t * 4;   // mt 2,3

    for (int j8 = 0; j8 < 128; j8++) {
        const uint32_t jb32 = (uint32_t)j8 << 8;
        const uint32_t jb2  = (uint32_t)j8 << 4;
        const uint32_t kb0 = *(const uint32_t*)(kbase + jb32 + koff0);
        const uint32_t kb1 = *(const uint32_t*)(kbase + jb32 + koff1);
        const uint32_t vb0 = *(const uint32_t*)(vbase0 + jb2);
        const uint32_t vb1 = *(const uint32_t*)(vbase1 + jb2);
        const float2 cw0 = h22f2(*(const uint32_t*)(cwb0 + jb2));
        const float2 cw1 = h22f2(*(const uint32_t*)(cwb1 + jb2));
        const float2 ch0 = h22f2(*(const uint32_t*)(chb0 + jb2));
        const float2 ch1 = h22f2(*(const uint32_t*)(chb1 + jb2));
        const float2 ch2 = h22f2(*(const uint32_t*)(chb2 + jb2));
        const float2 ch3 = h22f2(*(const uint32_t*)(chb3 + jb2));

#pragma unroll
        for (int mt = 0; mt < 4; mt++) {
            const float2 cA = (mt & 1) ? ch2 : ch0;
            const float2 cB = (mt & 1) ? ch3 : ch1;
            const float2 cw = (mt & 2) ? cw1 : cw0;
            float d0, d1, d2, d3;
            mmaS16(d0, d1, d2, d3, fa[mt][0], fa[mt][1], fa[mt][2], fa[mt][3],
                   kb0, kb1, nbA[mt], nbB[mt]);
            // fp32 exp path (accuracy-validated in R12)
            float p0 = ex2(d0 + cA.x + cw.x);
            float p1 = ex2(d1 + cA.y + cw.y);
            float p2 = ex2(d2 + cB.x + cw.x);
            float p3 = ex2(d3 + cB.y + cw.y);
            const uint32_t P0 = hpacks(p1, p0);
            const uint32_t P1 = hpacks(p3, p2);
            mmaPV(O[mt][0], P0, P1, vb0);
            mmaPV(O[mt][1], P0, P1, vb1);
            mmaPV(L[mt],    P0, P1, ONES_H2);   // exact row sums -> l
        }
    }

    // ---- epilogue: O/l + fused LN partial stats ----
    float* ob = g_att + b * (NC * NN) + hh * (ND * NN);
    float s_ln = 0.f, ss_ln = 0.f;
#pragma unroll
    for (int mt = 0; mt < 4; mt++) {
        const float inv0 = 1.f / L[mt][0];
        const float inv1 = 1.f / L[mt][2];
        const int r0 = i0 + (mt << 4) + g;
        const int r1 = r0 + 8;
#pragma unroll
        for (int dn = 0; dn < 2; dn++) {
            const int c0 = dn * 8 + 2 * t;
            float v00 = O[mt][dn][0] * inv0;
            float v01 = O[mt][dn][1] * inv0;
            float v10 = O[mt][dn][2] * inv1;
            float v11 = O[mt][dn][3] * inv1;
            ob[c0 * NN + r0]       = v00;
            ob[(c0 + 1) * NN + r0] = v01;
            ob[c0 * NN + r1]       = v10;
            ob[(c0 + 1) * NN + r1] = v11;
            s_ln  += v00 + v01 + v10 + v11;
            ss_ln += v00 * v00 + v01 * v01 + v10 * v10 + v11 * v11;
        }
    }
    // deterministic CTA-level reduce of (s, ss)
#pragma unroll
    for (int off = 16; off > 0; off >>= 1) {
        s_ln  += __shfl_xor_sync(0xffffffffu, s_ln, off);
        ss_ln += __shfl_xor_sync(0xffffffffu, ss_ln, off);
    }
    __syncthreads();   // tables no longer needed; reuse RH
    if (lane == 0) { RH[warp * 2] = s_ln; RH[warp * 2 + 1] = ss_ln; }
    __syncthreads();
    if (tid == 0) {
        float s = 0.f, ss = 0.f;
#pragma unroll
        for (int w2 = 0; w2 < 16; w2++) { s += RH[w2 * 2]; ss += RH[w2 * 2 + 1]; }
        g_lnpart[blockIdx.x * 2]     = s;
        g_lnpart[blockIdx.x * 2 + 1] = ss;
    }
}

// =====================================================================
// K3: x channel stats + CBAM MLP (LN scan fused into attn)
// =====================================================================
__global__ void __launch_bounds__(256)
stats_kernel(const float* __restrict__ x,
             const float* __restrict__ ca_w1, const float* __restrict__ ca_b1,
             const float* __restrict__ ca_w2, const float* __restrict__ ca_b2)
{
    const int b = blockIdx.x, tid = threadIdx.x;
    __shared__ float r1[256], r2[256];
    __shared__ float savg[64], smx2[64], hid[8];

    {
        int c = tid >> 2, qq = tid & 3;
        const float* xc = x + b * (NC * NN) + c * NN + qq * 256;
        float sa = 0.f, mx = -3.4e38f;
        for (int t2 = 0; t2 < 256; t2++) {
            float v = xc[t2];
            sa += v;
            mx = fmaxf(mx, v);
        }
        r1[tid] = sa; r2[tid] = mx;
    }
    __syncthreads();
    if (tid < 64) {
        float av = 0.f, m = -3.4e38f;
        for (int q2 = 0; q2 < 4; q2++) {
            av += r1[tid * 4 + q2];
            m = fmaxf(m, r2[tid * 4 + q2]);
        }
        savg[tid] = av * (1.f / 1024.f);
        smx2[tid] = m;
    }
    __syncthreads();
    if (tid < 8) {
        int r = tid & 3;
        const float* src = (tid < 4) ? savg : smx2;
        float h = ca_b1[r];
        for (int c2 = 0; c2 < 64; c2++) h += ca_w1[r * 64 + c2] * src[c2];
        hid[tid] = fmaxf(h, 0.f);
    }
    __syncthreads();
    if (tid < 64) {
        float o = 2.f * ca_b2[tid];
        for (int r = 0; r < 4; r++) o += ca_w2[tid * 4 + r] * (hid[r] + hid[4 + r]);
        g_chatt[b * NC + tid] = 1.f / (1.f + __expf(-o));
    }
}

// =====================================================================
// K4a: CBAM spatial map — 4 CTAs per batch
// =====================================================================
__global__ void __launch_bounds__(1024)
spatial_kernel(const float* __restrict__ x,
               const float* __restrict__ sa_w, const float* __restrict__ sa_b)
{
    const int b = blockIdx.x >> 2, qd = blockIdx.x & 3, tid = threadIdx.x;
    __shared__ float fm[NN], fx[NN], chs[64], wsh[98];
    if (tid < 64) chs[tid] = g_chatt[b * NC + tid];
    if (tid < 98) wsh[tid] = sa_w[tid];
    __syncthreads();

    {
        const float* xb = x + b * (NC * NN) + tid;
        float s = 0.f, m = -3.4e38f;
#pragma unroll
        for (int c = 0; c < 64; c++) {
            float v = chs[c] * xb[c * NN];
            s += v;
            m = fmaxf(m, v);
        }
        fm[tid] = s * (1.f / 64.f);
        fx[tid] = m;
    }
    __syncthreads();

    if (tid < 256) {
        const int iw = (qd << 3) + (tid >> 5), ih = tid & 31;
        float o = sa_b[0];
#pragma unroll
        for (int ky = 0; ky < 7; ky++) {
            int y = iw + ky - 3;
            if ((unsigned)y < 32u) {
#pragma unroll
                for (int kx = 0; kx < 7; kx++) {
                    int xx2 = ih + kx - 3;
                    if ((unsigned)xx2 < 32u) {
                        int fi = y * 32 + xx2;
                        o += wsh[ky * 7 + kx] * fm[fi] + wsh[49 + ky * 7 + kx] * fx[fi];
                    }
                }
            }
        }
        g_sp[b * NN + iw * 32 + ih] = 1.f / (1.f + __expf(-o));
    }
}

// =====================================================================
// K4b: final fuse — LN mu/rstd from the 4 per-head partials
// =====================================================================
__global__ void __launch_bounds__(256)
final_kernel(const float* __restrict__ x,
             const float* __restrict__ ln_g, const float* __restrict__ ln_b,
             float* __restrict__ out)
{
    int idx = blockIdx.x * 256 + threadIdx.x;
    int b  = idx >> 16;
    int cn = idx & 65535;
    int c  = cn >> 10;
    int n  = cn & 1023;

    float s = 0.f, ss = 0.f;
#pragma unroll
    for (int h = 0; h < 4; h++) {
        s  += g_lnpart[(b * 4 + h) * 2];
        ss += g_lnpart[(b * 4 + h) * 2 + 1];
    }
    float mu   = s * (1.f / 65536.f);
    float var  = ss * (1.f / 65536.f) - mu * mu;
    float rstd = rsqrtf(var + 1e-5f);

    float xv = x[idx];
    float av = g_att[idx];
    float ln = (av - mu) * rstd * ln_g[cn] + ln_b[cn];
    out[idx] = ln + 2.f * xv + g_sp[b * NN + n] * g_chatt[b * NC + c] * xv;
}

// =====================================================================
extern "C" void kernel_launch(void* const* d_in, const int* in_sizes, int n_in,
                              void* d_out, int out_size)
{
    const float* x     = (const float*)d_in[0];
    const float* Wq    = (const float*)d_in[1];
    const float* bq    = (const float*)d_in[2];
    const float* Wk    = (const float*)d_in[3];
    const float* bk    = (const float*)d_in[4];
    const float* Wv    = (const float*)d_in[5];
    const float* bv    = (const float*)d_in[6];
    const float* rel_h = (const float*)d_in[7];
    const float* rel_w = (const float*)d_in[8];
    const float* ln_g  = (const float*)d_in[9];
    const float* ln_b  = (const float*)d_in[10];
    const float* ca_w1 = (const float*)d_in[11];
    const float* ca_b1 = (const float*)d_in[12];
    const float* ca_w2 = (const float*)d_in[13];
    const float* ca_b2 = (const float*)d_in[14];
    const float* sa_w  = (const float*)d_in[15];
    const float* sa_b  = (const float*)d_in[16];
    float* out = (float*)d_out;

    const int smem1 = (64 * 256 + 3 * 64 * 66) * (int)sizeof(float);
    cudaFuncSetAttribute(qkv_kernel,     cudaFuncAttributeMaxDynamicSharedMemorySize, smem1);
    cudaFuncSetAttribute(attn_fa_kernel, cudaFuncAttributeMaxDynamicSharedMemorySize, SM2_TOT);

    qkv_kernel<<<NB * 4, 512, smem1>>>(x, Wq, bq, Wk, bk, Wv, bv);
    attn_fa_kernel<<<NB * NHEADS, 512, SM2_TOT>>>(rel_h, rel_w);
    stats_kernel<<<NB, 256>>>(x, ca_w1, ca_b1, ca_w2, ca_b2);
    spatial_kernel<<<NB * 4, 1024>>>(x, sa_w, sa_b);
    final_kernel<<<(NB * NC * NN) / 256, 256>>>(x, ln_g, ln_b, out);
}